// round 10
// baseline (speedup 1.0000x reference)
#include <cuda_runtime.h>

#define HID  128
#define MH   64
#define D32  32
#define OUTD 128
#define NB1  256   // k1 grid: (bg 128) x (k-half 2)
#define NB3  256   // k3 grid: (bg 128) x (o-half 2)

// ---- device globals (no allocation allowed) ----
__device__ float g_part[128 * 128]; // [bg][0:64)=hid, [64:96)=a, [96:128)=c
__device__ float g_final[192];      // [0:32)=S, [32:64)=T, [64:192)=K
__device__ float g_dummy[512];      // sink for L2-warm prefetch
__device__ int   g_cnt;             // ticket; reset by reducer each replay

// ========== k1: k-split hidden GEMM + partials; last block reduces ==========
__global__ void __launch_bounds__(512) k1(
    const float* __restrict__ hs,
    const float* __restrict__ obs1,
    const float* __restrict__ obs,
    const float* __restrict__ W_sp,
    const float* __restrict__ b_sp,
    const float* __restrict__ W_vel,
    const float* __restrict__ b_vel,
    const float* __restrict__ W_hid,
    const float* __restrict__ b_hid,
    const float* __restrict__ W_out,
    const float* __restrict__ b_out)
{
    __shared__ float wS[HID][32];   // 16 KB, [c][k_local]; tail scratch aliases
    __shared__ float hsS[8][HID];   // 4 KB
    __shared__ float bhS[32];
    __shared__ float sa[8][D32];    // 1 KB
    __shared__ float sc[8][D32];    // 1 KB
    __shared__ float p[2][8][32];   // 2 KB  [c-half][row][k]
    __shared__ float red[8][32];    // 1 KB
    __shared__ int   isLast;

    int b = blockIdx.x, t = threadIdx.x;
    int kh = b & 1, bg = b >> 1;
    int row0 = bg * 8;

    // ---- staging: ALL loads independent, one latency wave ----
    #pragma unroll
    for (int j = 0; j < 2; j++) {   // wS: 1024 float4, 2 per thread
        int idx = t + 512 * j;
        int c = idx >> 3, q = idx & 7;
        ((float4*)wS)[idx] =
            *(const float4*)(W_hid + c * MH + kh * 32 + q * 4);
    }
    if (t < 32) bhS[t] = b_hid[kh * 32 + t];

    if (t < 256) {                  // hs tile: 256 float4
        ((float4*)hsS)[t] = ((const float4*)(hs + row0 * HID))[t];
    } else if (kh == 0) {           // projections (kh=0 blocks only)
        int tt = t - 256;           // 8 rows x 32 d
        int row = tt >> 5, d = tt & 31;
        int i = row0 + row;
        float2 oo = ((const float2*)obs)[i];
        float2 o1 = ((const float2*)obs1)[i];
        sa[row][d] = fmaf(oo.x, W_sp[d], oo.y * W_sp[D32 + d]);
        float vx = 4.f * (oo.x - o1.x), vy = 4.f * (oo.y - o1.y);
        sc[row][d] = fmaf(vx, W_vel[d], vy * W_vel[D32 + d]);
    }
    __syncthreads();

    {   // GEMM: thread = k(32) x row(8) x ch(2); 64 FMA, single acc
        int k = t & 31, row = (t >> 5) & 7, ch = t >> 8;
        const float* wp = &wS[ch * 64][k];   // bank = k (conflict-free)
        const float* hp = &hsS[row][ch * 64];
        float acc = 0.f;
        #pragma unroll
        for (int c = 0; c < 64; c++)
            acc = fmaf(hp[c], wp[c * 32], acc);  // hp broadcast
        p[ch][row][k] = acc;
    }
    __syncthreads();

    if (t < 256) {                  // combine c-halves + bias + relu
        int k = t & 31, row = t >> 5;
        float v = bhS[k] + p[0][row][k] + p[1][row][k];
        red[row][k] = fmaxf(v, 0.f);
    }
    __syncthreads();

    if (t < 32) {                   // row-max for this block's 32 ks
        float m = red[0][t];
        #pragma unroll
        for (int r = 1; r < 8; r++) m = fmaxf(m, red[r][t]);
        g_part[bg * 128 + kh * 32 + t] = m;
    } else if (kh == 0 && t >= 64 && t < 96) {
        int d = t - 64;
        float m = sa[0][d];
        #pragma unroll
        for (int r = 1; r < 8; r++) m = fmaxf(m, sa[r][d]);
        g_part[bg * 128 + 64 + d] = m;
    } else if (kh == 0 && t >= 96 && t < 128) {
        int d = t - 96;
        float m = sc[0][d];
        #pragma unroll
        for (int r = 1; r < 8; r++) m = fmaxf(m, sc[r][d]);
        g_part[bg * 128 + 96 + d] = m;
    }
    __threadfence();
    if (t == 0) isLast = (atomicAdd(&g_cnt, 1) == NB1 - 1);
    __syncthreads();
    if (!isLast) return;

    // ======= reducer tail (only the LAST-arriving block) =======
    float* red2  = &wS[0][0];        // [4][128]
    float* hmS   = red2 + 512;       // [64]
    float* biasS = hmS + 64;         // [192]
    float* kred  = biasS + 192;      // [4][128]
    __syncthreads();

    if (t < 192)
        biasS[t] = (t < 32) ? b_sp[t] : (t < 64) ? b_vel[t - 32] : b_out[t - 64];

    {   // reduce 128 bg-partials: 128 cols x 4 groups x 32 rows (independent)
        int col = t & 127, grp = t >> 7;
        const float* pp = g_part + grp * 32 * 128 + col;
        float m = -3.4e38f;
        #pragma unroll
        for (int q = 0; q < 32; q++) m = fmaxf(m, __ldcg(&pp[q * 128]));
        red2[grp * 128 + col] = m;
    }
    {   // warm W_out[0:64] into L2 for k3 (independent, same wave)
        float dummy = 0.f;
        #pragma unroll
        for (int j = 0; j < 16; j++) dummy += __ldg(&W_out[j * 512 + t]);
        g_dummy[t] = dummy;
    }
    __syncthreads();
    if (t < 128) {
        float v = fmaxf(fmaxf(red2[t], red2[128 + t]),
                        fmaxf(red2[256 + t], red2[384 + t]));
        if (t < 64) hmS[t] = v;
        else        g_final[t - 64] = v + biasS[t - 64];   // S then T
    }
    __syncthreads();
    {   // K[o] = b_out[o] + sum_k hm[k]*W_out[64+k][o]
        int o = t & 127, khh = t >> 7;
        float acc = 0.f;
        #pragma unroll
        for (int j = 0; j < 16; j++) {
            int k = khh * 16 + j;
            acc = fmaf(hmS[k], __ldg(&W_out[(64 + k) * OUTD + o]), acc);
        }
        kred[khh * 128 + o] = acc;
    }
    __syncthreads();
    if (t < 128)
        g_final[64 + t] = biasS[64 + t] + kred[t] + kred[128 + t]
                                        + kred[256 + t] + kred[384 + t];
    if (t == 0) g_cnt = 0;          // reset ticket (deterministic replays)
}

// ========== k3: o-split output GEMM, one thread per (o,row) ==========
__global__ void __launch_bounds__(512) k3(
    const float* __restrict__ obs1,
    const float* __restrict__ obs,
    const float* __restrict__ W_sp,
    const float* __restrict__ W_vel,
    const float* __restrict__ W_out,
    float* __restrict__ out)
{
    __shared__ float woS[64][64];   // 16 KB, [d][o_local]
    __shared__ float SS[D32], TS[D32], KS[64];
    __shared__ float f[8][MH];      // 2 KB
    int b = blockIdx.x, t = threadIdx.x;
    int oh = b & 1, bg = b >> 1;
    int row0 = bg * 8;

    // ---- staging: all independent loads, one wave (L2-hot) ----
    #pragma unroll
    for (int j = 0; j < 2; j++) {   // woS: 1024 float4, 2 per thread
        int idx = t + 512 * j;
        int d = idx >> 4, q = idx & 15;
        ((float4*)woS)[idx] =
            *(const float4*)(W_out + d * OUTD + oh * 64 + q * 4);
    }

    int frow = t >> 6, fd = t & 63;
    int fi = row0 + frow;
    float2 oo = ((const float2*)obs)[fi];   // L2-hot
    float2 o1 = ((const float2*)obs1)[fi];

    if (t < 128) {
        if (t < 32)       SS[t] = g_final[t];
        else if (t < 64)  TS[t - 32] = g_final[t];
        else              KS[t - 64] = g_final[64 + oh * 64 + (t - 64)];
    }
    __syncthreads();

    {   // features: 512 slots = 8 rows x 64 d, one per thread
        float val;
        if (fd < D32) {
            float a = fmaf(oo.x, W_sp[fd], oo.y * W_sp[D32 + fd]);
            val = fmaxf(SS[fd] - a, 0.f);
        } else {
            int dd = fd - D32;
            float vx = 4.f * (oo.x - o1.x), vy = 4.f * (oo.y - o1.y);
            float c = fmaf(vx, W_vel[dd], vy * W_vel[D32 + dd]);
            val = fmaxf(TS[dd] - c, 0.f);
        }
        f[frow][fd] = val;
    }
    __syncthreads();

    {   // GEMM: thread = o(64) x row(8); full 64-d accumulation, no combine
        int o = t & 63, row = t >> 6;
        const float* wp = &woS[0][o];       // bank = o%32 (conflict-free)
        const float* fp = &f[row][0];       // broadcast
        float acc = KS[o];
        #pragma unroll
        for (int d = 0; d < 64; d++)
            acc = fmaf(fp[d], wp[d * 64], acc);
        out[(row0 + row) * OUTD + oh * 64 + o] = acc;   // coalesced
    }
}

extern "C" void kernel_launch(void* const* d_in, const int* in_sizes, int n_in,
                              void* d_out, int out_size)
{
    const float* hs    = (const float*)d_in[0];
    const float* obs1  = (const float*)d_in[1];
    const float* obs   = (const float*)d_in[2];
    const float* W_sp  = (const float*)d_in[3];
    const float* b_sp  = (const float*)d_in[4];
    const float* W_vel = (const float*)d_in[5];
    const float* b_vel = (const float*)d_in[6];
    const float* W_hid = (const float*)d_in[7];
    const float* b_hid = (const float*)d_in[8];
    const float* W_out = (const float*)d_in[9];
    const float* b_out = (const float*)d_in[10];
    float* out = (float*)d_out;

    k1<<<NB1, 512>>>(hs, obs1, obs, W_sp, b_sp, W_vel, b_vel,
                     W_hid, b_hid, W_out, b_out);
    k3<<<NB3, 512>>>(obs1, obs, W_sp, W_vel, W_out, out);
}

// round 11
// speedup vs baseline: 1.0821x; 1.0821x over previous
#include <cuda_runtime.h>

#define HID  128
#define MH   64
#define D32  32
#define OUTD 128
#define NB   128   // k1/k3 grid; 8 rows per block

// ---- device globals (no allocation allowed) ----
__device__ float g_part[NB * 128]; // [b][0:64)=hid, [64:96)=a, [96:128)=c
__device__ float g_final[192];     // [0:32)=S, [32:64)=T, [64:192)=K
__device__ float g_dummy[512];     // sink for L2-warm prefetch
__device__ int   g_cnt;            // ticket; reset by reducer each replay

// ========== k1: smem-staged hidden GEMM + partials; last block reduces ==========
// (identical to the R9 version that passed at 13.06us)
__global__ void __launch_bounds__(512) k1(
    const float* __restrict__ hs,
    const float* __restrict__ obs1,
    const float* __restrict__ obs,
    const float* __restrict__ W_sp,
    const float* __restrict__ b_sp,
    const float* __restrict__ W_vel,
    const float* __restrict__ b_vel,
    const float* __restrict__ W_hid,
    const float* __restrict__ b_hid,
    const float* __restrict__ W_out,
    const float* __restrict__ b_out)
{
    __shared__ float wS[HID][MH];   // 32 KB, [c][k]; tail scratch aliases here
    __shared__ float hsS[8][HID];   // 4 KB
    __shared__ float bhS[MH];
    __shared__ float sa[8][D32];    // 1 KB
    __shared__ float sc[8][D32];    // 1 KB
    __shared__ float p0[8][MH];     // 2 KB
    __shared__ float p1[8][MH];     // 2 KB
    __shared__ float red[4][MH];    // 1 KB
    __shared__ int   isLast;

    int b = blockIdx.x, t = threadIdx.x;
    int row0 = b * 8;

    // ---- staging: ALL loads independent, one latency wave ----
    #pragma unroll
    for (int j = 0; j < 4; j++)     // W_hid: 2048 float4, 4 per thread
        ((float4*)wS)[t + 512 * j] = ((const float4*)W_hid)[t + 512 * j];

    if (t < 64) bhS[t] = b_hid[t];

    if (t < 256) {                  // hs tile: 256 float4
        ((float4*)hsS)[t] = ((const float4*)(hs + row0 * HID))[t];
    } else {                        // projections: row = tt>>5, d = tt&31
        int tt = t - 256;
        int row = tt >> 5, d = tt & 31;
        int i = row0 + row;
        float2 oo = ((const float2*)obs)[i];
        float2 o1 = ((const float2*)obs1)[i];
        sa[row][d] = fmaf(oo.x, W_sp[d], oo.y * W_sp[D32 + d]);
        float vx = 4.f * (oo.x - o1.x), vy = 4.f * (oo.y - o1.y);
        sc[row][d] = fmaf(vx, W_vel[d], vy * W_vel[D32 + d]);
    }
    __syncthreads();

    {   // GEMM from smem: 512 thr = k(64) x ch(2 c-halves) x rg(4 row-pairs)
        int k = t & 63, g = t >> 6;          // g = rg*2 + ch
        int ch = g & 1, rg = g >> 1;
        const float* wp = &wS[ch * 64][k];   // bank = k%32 (conflict-free)
        const float* h0 = &hsS[rg * 2][ch * 64];
        const float* h1 = &hsS[rg * 2 + 1][ch * 64];
        float a0 = 0.f, a1 = 0.f;
        #pragma unroll
        for (int c = 0; c < 64; c++) {
            float w = wp[c * MH];
            a0 = fmaf(h0[c], w, a0);         // smem broadcast
            a1 = fmaf(h1[c], w, a1);
        }
        p0[g][k] = a0;
        p1[g][k] = a1;
    }
    __syncthreads();

    if (t < 256) {                  // combine c-halves, relu, max over 2 rows
        int k = t & 63, rg = t >> 6;
        float bk = bhS[k];
        float a0 = bk + p0[rg * 2][k] + p0[rg * 2 + 1][k];
        float a1 = bk + p1[rg * 2][k] + p1[rg * 2 + 1][k];
        red[rg][k] = fmaxf(fmaxf(a0, a1), 0.f);
    }
    __syncthreads();

    if (t < 64) {
        g_part[b * 128 + t] = fmaxf(fmaxf(red[0][t], red[1][t]),
                                    fmaxf(red[2][t], red[3][t]));
    } else if (t < 96) {
        int d = t - 64;
        float m = sa[0][d];
        #pragma unroll
        for (int r = 1; r < 8; r++) m = fmaxf(m, sa[r][d]);
        g_part[b * 128 + t] = m;
    } else if (t < 128) {
        int d = t - 96;
        float m = sc[0][d];
        #pragma unroll
        for (int r = 1; r < 8; r++) m = fmaxf(m, sc[r][d]);
        g_part[b * 128 + t] = m;
    }
    __threadfence();
    if (t == 0) isLast = (atomicAdd(&g_cnt, 1) == NB - 1);
    __syncthreads();
    if (!isLast) return;

    // ======= reducer tail (only the LAST-arriving block; others exited) =======
    float* red2  = &wS[0][0];        // [4][128]
    float* hmS   = red2 + 512;       // [64]
    float* biasS = hmS + 64;         // [192]
    float* kred  = biasS + 192;      // [4][128]
    __syncthreads();

    if (t < 192)
        biasS[t] = (t < 32) ? b_sp[t] : (t < 64) ? b_vel[t - 32] : b_out[t - 64];

    {   // reduce NB=128 partials: 128 cols x 4 groups x 32 rows (independent)
        int col = t & 127, grp = t >> 7;
        const float* p = g_part + grp * 32 * 128 + col;
        float m = -3.4e38f;
        #pragma unroll
        for (int q = 0; q < 32; q++) m = fmaxf(m, __ldcg(&p[q * 128]));
        red2[grp * 128 + col] = m;
    }
    {   // warm W_out[0:64] into L2 for k3 (independent, same wave)
        float dummy = 0.f;
        #pragma unroll
        for (int j = 0; j < 16; j++) dummy += __ldg(&W_out[j * 512 + t]);
        g_dummy[t] = dummy;
    }
    __syncthreads();
    if (t < 128) {
        float v = fmaxf(fmaxf(red2[t], red2[128 + t]),
                        fmaxf(red2[256 + t], red2[384 + t]));
        if (t < 64) hmS[t] = v;
        else        g_final[t - 64] = v + biasS[t - 64];   // S then T
    }
    __syncthreads();
    {   // K[o] = b_out[o] + sum_k hm[k]*W_out[64+k][o]; 16 k's per thread
        int o = t & 127, kh = t >> 7;
        float acc = 0.f;
        #pragma unroll
        for (int j = 0; j < 16; j++) {
            int k = kh * 16 + j;
            acc = fmaf(hmS[k], __ldg(&W_out[(64 + k) * OUTD + o]), acc);
        }
        kred[kh * 128 + o] = acc;
    }
    __syncthreads();
    if (t < 128)
        g_final[64 + t] = biasS[64 + t] + kred[t] + kred[128 + t]
                                        + kred[256 + t] + kred[384 + t];
    if (t == 0) g_cnt = 0;          // reset ticket (deterministic replays)
}

// ========== k3: direct-__ldg output GEMM (R5 version, measured ~2.5-3us) ==========
__global__ void __launch_bounds__(512) k3(
    const float* __restrict__ obs1,
    const float* __restrict__ obs,
    const float* __restrict__ W_sp,
    const float* __restrict__ W_vel,
    const float* __restrict__ W_out,
    float* __restrict__ out)
{
    __shared__ float SS[D32], TS[D32], KS[OUTD];
    __shared__ float f[8][MH];        // 2 KB
    __shared__ float part[4][4][128]; // 8 KB [g][row_in_group][o]
    int b = blockIdx.x, t = threadIdx.x;
    int row0 = b * 8;

    if (t < 192) {
        float v = g_final[t];         // L2 hit
        if (t < 32)       SS[t] = v;
        else if (t < 64)  TS[t - 32] = v;
        else              KS[t - 64] = v;
    }
    __syncthreads();

    {   // features: 512 slots = 8 rows x 64 d, one per thread
        int row = t >> 6, d = t & 63;
        int i = row0 + row;
        float2 oo = ((const float2*)obs)[i];
        float val;
        if (d < D32) {
            float a = fmaf(oo.x, W_sp[d], oo.y * W_sp[D32 + d]);
            val = fmaxf(SS[d] - a, 0.f);
        } else {
            int dd = d - D32;
            float2 o1 = ((const float2*)obs1)[i];
            float vx = 4.f * (oo.x - o1.x), vy = 4.f * (oo.y - o1.y);
            float c = fmaf(vx, W_vel[dd], vy * W_vel[dd + D32 - D32 + D32]);
            // NOTE: W_vel is [2][32]: rows 0 and 1. Use explicit form below.
            c = fmaf(vx, W_vel[dd], vy * W_vel[D32 + dd]);
            val = fmaxf(TS[dd] - c, 0.f);
        }
        f[row][d] = val;
    }
    __syncthreads();

    {   // GEMM: 512 thr = o(128) x ch(2 d-halves) x rh(2 row-quads); L2-hot __ldg
        int o = t & 127, g = t >> 7;  // g = rh*2 + ch
        int ch = g & 1, rh = g >> 1;
        const float* wp = W_out + ch * 32 * OUTD + o;
        float acc[4] = {0.f, 0.f, 0.f, 0.f};
        #pragma unroll
        for (int d0 = 0; d0 < 32; d0 += 8) {
            float w[8];
            #pragma unroll
            for (int j = 0; j < 8; j++) w[j] = __ldg(&wp[(d0 + j) * OUTD]);
            #pragma unroll
            for (int j = 0; j < 8; j++) {
                #pragma unroll
                for (int r = 0; r < 4; r++)
                    acc[r] = fmaf(f[rh * 4 + r][ch * 32 + d0 + j], w[j], acc[r]);
            }
        }
        #pragma unroll
        for (int r = 0; r < 4; r++) part[g][r][o] = acc[r];
    }
    __syncthreads();

    {   // combine d-halves + K, write out: 1024 outputs, 2 per thread
        #pragma unroll
        for (int s = 0; s < 2; s++) {
            int slot = t + 512 * s;
            int row = slot >> 7, o = slot & 127;
            int rh = row >> 2, r = row & 3;
            out[(row0 + row) * OUTD + o] =
                KS[o] + part[rh * 2][r][o] + part[rh * 2 + 1][r][o];
        }
    }
}

extern "C" void kernel_launch(void* const* d_in, const int* in_sizes, int n_in,
                              void* d_out, int out_size)
{
    const float* hs    = (const float*)d_in[0];
    const float* obs1  = (const float*)d_in[1];
    const float* obs   = (const float*)d_in[2];
    const float* W_sp  = (const float*)d_in[3];
    const float* b_sp  = (const float*)d_in[4];
    const float* W_vel = (const float*)d_in[5];
    const float* b_vel = (const float*)d_in[6];
    const float* W_hid = (const float*)d_in[7];
    const float* b_hid = (const float*)d_in[8];
    const float* W_out = (const float*)d_in[9];
    const float* b_out = (const float*)d_in[10];
    float* out = (float*)d_out;

    k1<<<NB, 512>>>(hs, obs1, obs, W_sp, b_sp, W_vel, b_vel,
                    W_hid, b_hid, W_out, b_out);
    k3<<<NB, 512>>>(obs1, obs, W_sp, W_vel, W_out, out);
}

// round 12
// speedup vs baseline: 1.0980x; 1.0147x over previous
#include <cuda_runtime.h>

#define HID  128
#define MH   64
#define D32  32
#define OUTD 128
#define NB   128   // k1/k3 grid; 8 rows per block

// ---- device globals (no allocation allowed) ----
__device__ float g_part[NB * 128]; // [b][0:64)=hid, [64:96)=a, [96:128)=c
__device__ float g_final[192];     // [0:32)=S, [32:64)=T, [64:192)=K
__device__ float g_dummy[512];     // sink for L2-warm prefetch
__device__ int   g_cnt;            // ticket; reset by reducer each replay

// ========== k1: smem-staged hidden GEMM + partials; last block reduces ==========
// (identical to the R9/R11 version)
__global__ void __launch_bounds__(512) k1(
    const float* __restrict__ hs,
    const float* __restrict__ obs1,
    const float* __restrict__ obs,
    const float* __restrict__ W_sp,
    const float* __restrict__ b_sp,
    const float* __restrict__ W_vel,
    const float* __restrict__ b_vel,
    const float* __restrict__ W_hid,
    const float* __restrict__ b_hid,
    const float* __restrict__ W_out,
    const float* __restrict__ b_out)
{
    __shared__ float wS[HID][MH];   // 32 KB; tail scratch aliases here
    __shared__ float hsS[8][HID];   // 4 KB
    __shared__ float bhS[MH];
    __shared__ float sa[8][D32];    // 1 KB
    __shared__ float sc[8][D32];    // 1 KB
    __shared__ float p0[8][MH];     // 2 KB
    __shared__ float p1[8][MH];     // 2 KB
    __shared__ float red[4][MH];    // 1 KB
    __shared__ int   isLast;

    int b = blockIdx.x, t = threadIdx.x;
    int row0 = b * 8;

    #pragma unroll
    for (int j = 0; j < 4; j++)
        ((float4*)wS)[t + 512 * j] = ((const float4*)W_hid)[t + 512 * j];

    if (t < 64) bhS[t] = b_hid[t];

    if (t < 256) {
        ((float4*)hsS)[t] = ((const float4*)(hs + row0 * HID))[t];
    } else {
        int tt = t - 256;
        int row = tt >> 5, d = tt & 31;
        int i = row0 + row;
        float2 oo = ((const float2*)obs)[i];
        float2 o1 = ((const float2*)obs1)[i];
        sa[row][d] = fmaf(oo.x, W_sp[d], oo.y * W_sp[D32 + d]);
        float vx = 4.f * (oo.x - o1.x), vy = 4.f * (oo.y - o1.y);
        sc[row][d] = fmaf(vx, W_vel[d], vy * W_vel[D32 + d]);
    }
    __syncthreads();

    {
        int k = t & 63, g = t >> 6;
        int ch = g & 1, rg = g >> 1;
        const float* wp = &wS[ch * 64][k];
        const float* h0 = &hsS[rg * 2][ch * 64];
        const float* h1 = &hsS[rg * 2 + 1][ch * 64];
        float a0 = 0.f, a1 = 0.f;
        #pragma unroll
        for (int c = 0; c < 64; c++) {
            float w = wp[c * MH];
            a0 = fmaf(h0[c], w, a0);
            a1 = fmaf(h1[c], w, a1);
        }
        p0[g][k] = a0;
        p1[g][k] = a1;
    }
    __syncthreads();

    if (t < 256) {
        int k = t & 63, rg = t >> 6;
        float bk = bhS[k];
        float a0 = bk + p0[rg * 2][k] + p0[rg * 2 + 1][k];
        float a1 = bk + p1[rg * 2][k] + p1[rg * 2 + 1][k];
        red[rg][k] = fmaxf(fmaxf(a0, a1), 0.f);
    }
    __syncthreads();

    if (t < 64) {
        g_part[b * 128 + t] = fmaxf(fmaxf(red[0][t], red[1][t]),
                                    fmaxf(red[2][t], red[3][t]));
    } else if (t < 96) {
        int d = t - 64;
        float m = sa[0][d];
        #pragma unroll
        for (int r = 1; r < 8; r++) m = fmaxf(m, sa[r][d]);
        g_part[b * 128 + t] = m;
    } else if (t < 128) {
        int d = t - 96;
        float m = sc[0][d];
        #pragma unroll
        for (int r = 1; r < 8; r++) m = fmaxf(m, sc[r][d]);
        g_part[b * 128 + t] = m;
    }
    __threadfence();
    if (t == 0) isLast = (atomicAdd(&g_cnt, 1) == NB - 1);
    __syncthreads();
    if (!isLast) return;

    // ======= reducer tail (last-arriving block only) =======
    float* red2  = &wS[0][0];
    float* hmS   = red2 + 512;
    float* biasS = hmS + 64;
    float* kred  = biasS + 192;
    __syncthreads();

    if (t < 192)
        biasS[t] = (t < 32) ? b_sp[t] : (t < 64) ? b_vel[t - 32] : b_out[t - 64];

    {
        int col = t & 127, grp = t >> 7;
        const float* p = g_part + grp * 32 * 128 + col;
        float m = -3.4e38f;
        #pragma unroll
        for (int q = 0; q < 32; q++) m = fmaxf(m, __ldcg(&p[q * 128]));
        red2[grp * 128 + col] = m;
    }
    {
        float dummy = 0.f;
        #pragma unroll
        for (int j = 0; j < 16; j++) dummy += __ldg(&W_out[j * 512 + t]);
        g_dummy[t] = dummy;
    }
    __syncthreads();
    if (t < 128) {
        float v = fmaxf(fmaxf(red2[t], red2[128 + t]),
                        fmaxf(red2[256 + t], red2[384 + t]));
        if (t < 64) hmS[t] = v;
        else        g_final[t - 64] = v + biasS[t - 64];
    }
    __syncthreads();
    {
        int o = t & 127, kh = t >> 7;
        float acc = 0.f;
        #pragma unroll
        for (int j = 0; j < 16; j++) {
            int k = kh * 16 + j;
            acc = fmaf(hmS[k], __ldg(&W_out[(64 + k) * OUTD + o]), acc);
        }
        kred[kh * 128 + o] = acc;
    }
    __syncthreads();
    if (t < 128)
        g_final[64 + t] = biasS[64 + t] + kred[t] + kred[128 + t]
                                        + kred[256 + t] + kred[384 + t];
    if (t == 0) g_cnt = 0;
}

// ========== k3: ONE load wave (W in registers) + 2 syncs ==========
__global__ void __launch_bounds__(512) k3(
    const float* __restrict__ obs1,
    const float* __restrict__ obs,
    const float* __restrict__ W_sp,
    const float* __restrict__ W_vel,
    const float* __restrict__ W_out,
    float* __restrict__ out)
{
    __shared__ float KS[OUTD];
    __shared__ float f[8][MH];        // 2 KB
    __shared__ float part[4][4][128]; // 8 KB [g][row_in_group][o]
    int b = blockIdx.x, t = threadIdx.x;
    int row0 = b * 8;

    // GEMM role (used later): o(128) x ch(2 d-halves) x rh(2 row-quads)
    int o = t & 127, g = t >> 7;
    int ch = g & 1, rh = g >> 1;

    // ===== phase 0: ALL global loads, mutually independent, one wave =====
    float w[32];                      // this thread's 32 W_out values (L2-warm)
    {
        const float* wp = W_out + ch * 32 * OUTD + o;
        #pragma unroll
        for (int j = 0; j < 32; j++) w[j] = __ldg(&wp[j * OUTD]);
    }

    // feature role: row = t>>6 (8 rows), fd = t&63
    int frow = t >> 6, fd = t & 63;
    int fi = row0 + frow;
    float2 oo = ((const float2*)obs)[fi];    // L2-hot (k1 read it)
    float2 o1 = ((const float2*)obs1)[fi];
    float stv = g_final[fd];                 // S[fd] (fd<32) or T[fd-32] — direct
    if (t < 128) KS[t] = g_final[64 + t];    // K staged (independent)

    // feature value (no sync needed before this; all inputs are this thread's)
    float val;
    if (fd < D32) {
        float a = fmaf(oo.x, W_sp[fd], oo.y * W_sp[D32 + fd]);
        val = fmaxf(stv - a, 0.f);
    } else {
        int dd = fd - D32;
        float vx = 4.f * (oo.x - o1.x), vy = 4.f * (oo.y - o1.y);
        float c = fmaf(vx, W_vel[dd], vy * W_vel[D32 + dd]);
        val = fmaxf(stv - c, 0.f);
    }
    f[frow][fd] = val;
    __syncthreads();                  // sync #1

    // ===== GEMM: registers w[] x smem f; zero global waves =====
    {
        float acc[4] = {0.f, 0.f, 0.f, 0.f};
        #pragma unroll
        for (int j = 0; j < 32; j++) {
            #pragma unroll
            for (int r = 0; r < 4; r++)
                acc[r] = fmaf(f[rh * 4 + r][ch * 32 + j], w[j], acc[r]);
        }
        #pragma unroll
        for (int r = 0; r < 4; r++) part[g][r][o] = acc[r];
    }
    __syncthreads();                  // sync #2

    // ===== combine d-halves + K, write out: 1024 outputs, 2 per thread =====
    #pragma unroll
    for (int s = 0; s < 2; s++) {
        int slot = t + 512 * s;
        int row = slot >> 7, oo2 = slot & 127;
        int rh2 = row >> 2, r = row & 3;
        out[(row0 + row) * OUTD + oo2] =
            KS[oo2] + part[rh2 * 2][r][oo2] + part[rh2 * 2 + 1][r][oo2];
    }
}

extern "C" void kernel_launch(void* const* d_in, const int* in_sizes, int n_in,
                              void* d_out, int out_size)
{
    const float* hs    = (const float*)d_in[0];
    const float* obs1  = (const float*)d_in[1];
    const float* obs   = (const float*)d_in[2];
    const float* W_sp  = (const float*)d_in[3];
    const float* b_sp  = (const float*)d_in[4];
    const float* W_vel = (const float*)d_in[5];
    const float* b_vel = (const float*)d_in[6];
    const float* W_hid = (const float*)d_in[7];
    const float* b_hid = (const float*)d_in[8];
    const float* W_out = (const float*)d_in[9];
    const float* b_out = (const float*)d_in[10];
    float* out = (float*)d_out;

    k1<<<NB, 512>>>(hs, obs1, obs, W_sp, b_sp, W_vel, b_vel,
                    W_hid, b_hid, W_out, b_out);
    k3<<<NB, 512>>>(obs1, obs, W_sp, W_vel, W_out, out);
}

// round 13
// speedup vs baseline: 1.1458x; 1.0435x over previous
#include <cuda_runtime.h>

#define HID  128
#define MH   64
#define D32  32
#define OUTD 128
#define NB   128   // grid; 8 rows per block; <= SM count (co-resident)

// ---- device globals (no allocation allowed) ----
__device__ float        g_part[NB * 128]; // [b][0:64)=hid, [64:96)=a, [96:128)=c
__device__ float        g_final[192];     // [0:32)=S, [32:64)=T, [64:192)=K
__device__ int          g_cnt;            // phase-A ticket (reducer resets)
__device__ int          g_cnt2;           // post-spin ticket (last resets flag)
__device__ volatile int g_flag;           // reducer -> consumers

__global__ void __launch_bounds__(512) kf(
    const float* __restrict__ hs,
    const float* __restrict__ obs1,
    const float* __restrict__ obs,
    const float* __restrict__ W_sp,
    const float* __restrict__ b_sp,
    const float* __restrict__ W_vel,
    const float* __restrict__ b_vel,
    const float* __restrict__ W_hid,
    const float* __restrict__ b_hid,
    const float* __restrict__ W_out,
    const float* __restrict__ b_out,
    float* __restrict__ out)
{
    __shared__ float wS[HID][MH];   // 32 KB; tail + phase-C scratch alias here
    __shared__ float hsS[8][HID];   // 4 KB
    __shared__ float bhS[MH];
    __shared__ float sa[8][D32];    // 1 KB  (kept live for phase C)
    __shared__ float sc[8][D32];    // 1 KB  (kept live for phase C)
    __shared__ float p0[8][MH];     // 2 KB
    __shared__ float p1[8][MH];     // 2 KB
    __shared__ float red[4][MH];    // 1 KB
    __shared__ int   isLast;

    int b = blockIdx.x, t = threadIdx.x;
    int row0 = b * 8;

    // phase-C GEMM role: o(128) x ch(2 d-halves) x rh(2 row-quads)
    int o = t & 127, g4 = t >> 7;
    int ch = g4 & 1, rh = g4 >> 1;

    // ========== phase A staging: ALL loads independent, one wave ==========
    float w[32];                    // this thread's W_out[ch*32 + j][o] values
    {
        const float* wp = W_out + ch * 32 * OUTD + o;
        #pragma unroll
        for (int j = 0; j < 32; j++) w[j] = __ldg(&wp[j * OUTD]);
    }

    #pragma unroll
    for (int j = 0; j < 4; j++)     // W_hid: 2048 float4
        ((float4*)wS)[t + 512 * j] = ((const float4*)W_hid)[t + 512 * j];

    if (t < 64) bhS[t] = b_hid[t];

    if (t < 256) {
        ((float4*)hsS)[t] = ((const float4*)(hs + row0 * HID))[t];
    } else {
        int tt = t - 256;
        int row = tt >> 5, d = tt & 31;
        int i = row0 + row;
        float2 oo = ((const float2*)obs)[i];
        float2 o1 = ((const float2*)obs1)[i];
        sa[row][d] = fmaf(oo.x, W_sp[d], oo.y * W_sp[D32 + d]);
        float vx = 4.f * (oo.x - o1.x), vy = 4.f * (oo.y - o1.y);
        sc[row][d] = fmaf(vx, W_vel[d], vy * W_vel[D32 + d]);
    }
    __syncthreads();

    {   // hidden GEMM from smem: k(64) x ch2(2 c-halves) x rg(4 row-pairs)
        int k = t & 63, g = t >> 6;
        int ch2 = g & 1, rg = g >> 1;
        const float* wp = &wS[ch2 * 64][k];
        const float* h0 = &hsS[rg * 2][ch2 * 64];
        const float* h1 = &hsS[rg * 2 + 1][ch2 * 64];
        float a0 = 0.f, a1 = 0.f;
        #pragma unroll
        for (int c = 0; c < 64; c++) {
            float ww = wp[c * MH];
            a0 = fmaf(h0[c], ww, a0);
            a1 = fmaf(h1[c], ww, a1);
        }
        p0[g][k] = a0;
        p1[g][k] = a1;
    }
    __syncthreads();

    if (t < 256) {
        int k = t & 63, rg = t >> 6;
        float bk = bhS[k];
        float a0 = bk + p0[rg * 2][k] + p0[rg * 2 + 1][k];
        float a1 = bk + p1[rg * 2][k] + p1[rg * 2 + 1][k];
        red[rg][k] = fmaxf(fmaxf(a0, a1), 0.f);
    }
    __syncthreads();

    if (t < 64) {
        g_part[b * 128 + t] = fmaxf(fmaxf(red[0][t], red[1][t]),
                                    fmaxf(red[2][t], red[3][t]));
    } else if (t < 96) {
        int d = t - 64;
        float m = sa[0][d];
        #pragma unroll
        for (int r = 1; r < 8; r++) m = fmaxf(m, sa[r][d]);
        g_part[b * 128 + t] = m;
    } else if (t < 128) {
        int d = t - 96;
        float m = sc[0][d];
        #pragma unroll
        for (int r = 1; r < 8; r++) m = fmaxf(m, sc[r][d]);
        g_part[b * 128 + t] = m;
    }
    __threadfence();
    if (t == 0) isLast = (atomicAdd(&g_cnt, 1) == NB - 1);
    __syncthreads();

    // ========== reducer tail (last-arriving block only) ==========
    if (isLast) {
        float* red2  = &wS[0][0];    // [4][128] — aliases wS (done with weights)
        float* hmS   = red2 + 512;   // [64]
        float* biasS = hmS + 64;     // [192]
        float* kred  = biasS + 192;  // [4][128]

        if (t < 192)
            biasS[t] = (t < 32) ? b_sp[t]
                     : (t < 64) ? b_vel[t - 32] : b_out[t - 64];

        {   // reduce 128 partials: 128 cols x 4 groups x 32 rows (independent)
            int col = t & 127, grp = t >> 7;
            const float* p = g_part + grp * 32 * 128 + col;
            float m = -3.4e38f;
            #pragma unroll
            for (int q = 0; q < 32; q++) m = fmaxf(m, __ldcg(&p[q * 128]));
            red2[grp * 128 + col] = m;
        }
        __syncthreads();
        if (t < 128) {
            float v = fmaxf(fmaxf(red2[t], red2[128 + t]),
                            fmaxf(red2[256 + t], red2[384 + t]));
            if (t < 64) hmS[t] = v;
            else        g_final[t - 64] = v + biasS[t - 64];   // S then T
        }
        __syncthreads();
        {   // K[o] = b_out[o] + sum_k hm[k]*W_out[64+k][o]
            int oo = t & 127, kh = t >> 7;
            float acc = 0.f;
            #pragma unroll
            for (int j = 0; j < 16; j++) {
                int k = kh * 16 + j;
                acc = fmaf(hmS[k], __ldg(&W_out[(64 + k) * OUTD + oo]), acc);
            }
            kred[kh * 128 + oo] = acc;
        }
        __syncthreads();
        if (t < 128)
            g_final[64 + t] = biasS[64 + t] + kred[t] + kred[128 + t]
                                            + kred[256 + t] + kred[384 + t];
        if (t == 0) g_cnt = 0;       // reset phase-A ticket (reducer is last)
        __threadfence();
        if (t == 0) g_flag = 1;      // release consumers
    }

    // ========== spin (nanosleep backoff; blocks are all co-resident) ==========
    if (t == 0) {
        if (g_flag == 0) {
            while (g_flag == 0) __nanosleep(200);
        }
        // past the spin: last block resets the flag for the next graph replay
        if (atomicAdd(&g_cnt2, 1) == NB - 1) { g_flag = 0; g_cnt2 = 0; }
    }
    __syncthreads();

    // ========== phase C: features from live sa/sc, GEMM from registers ==========
    float* KS   = &wS[0][0] + 2048;  // [128] — clear of tail scratch [0,1280)
    float* fS   = KS + 128;          // [8][64] = 512 floats
    float* part = fS + 512;          // [4][4][128] = 2048 floats

    if (t < 128) KS[t] = __ldcg(&g_final[64 + t]);
    {   // feature: one slot per thread (8 rows x 64 d)
        int frow = t >> 6, fd = t & 63;
        float stv = __ldcg(&g_final[fd]);            // S[fd] or T[fd-32]
        float av  = (fd < D32) ? sa[frow][fd] : sc[frow][fd - D32];
        fS[frow * 64 + fd] = fmaxf(stv - av, 0.f);
    }
    __syncthreads();

    {   // GEMM: registers w[] x smem f
        float acc[4] = {0.f, 0.f, 0.f, 0.f};
        #pragma unroll
        for (int j = 0; j < 32; j++) {
            #pragma unroll
            for (int r = 0; r < 4; r++)
                acc[r] = fmaf(fS[(rh * 4 + r) * 64 + ch * 32 + j], w[j], acc[r]);
        }
        #pragma unroll
        for (int r = 0; r < 4; r++)
            part[(g4 * 4 + r) * 128 + o] = acc[r];
    }
    __syncthreads();

    {   // combine d-halves + K, write out: 1024 outputs, 2 per thread
        #pragma unroll
        for (int s = 0; s < 2; s++) {
            int slot = t + 512 * s;
            int row = slot >> 7, oo2 = slot & 127;
            int rh2 = row >> 2, r = row & 3;
            out[(row0 + row) * OUTD + oo2] =
                KS[oo2] + part[((rh2 * 2) * 4 + r) * 128 + oo2]
                        + part[((rh2 * 2 + 1) * 4 + r) * 128 + oo2];
        }
    }
}

extern "C" void kernel_launch(void* const* d_in, const int* in_sizes, int n_in,
                              void* d_out, int out_size)
{
    const float* hs    = (const float*)d_in[0];
    const float* obs1  = (const float*)d_in[1];
    const float* obs   = (const float*)d_in[2];
    const float* W_sp  = (const float*)d_in[3];
    const float* b_sp  = (const float*)d_in[4];
    const float* W_vel = (const float*)d_in[5];
    const float* b_vel = (const float*)d_in[6];
    const float* W_hid = (const float*)d_in[7];
    const float* b_hid = (const float*)d_in[8];
    const float* W_out = (const float*)d_in[9];
    const float* b_out = (const float*)d_in[10];
    float* out = (float*)d_out;

    kf<<<NB, 512>>>(hs, obs1, obs, W_sp, b_sp, W_vel, b_vel,
                    W_hid, b_hid, W_out, b_out, out);
}